// round 8
// baseline (speedup 1.0000x reference)
#include <cuda_runtime.h>
#include <cuda_bf16.h>
#include <mma.h>
#include <cstdint>

using namespace nvcuda;

#define N_ROWS 8192
#define DIM    512
#define KSEL   31   // k+1 entries kept per row

// Scratch (static device arrays; no allocs allowed).
__device__ float          g_emb[N_ROWS * DIM];   // exact fp32 normalized emb
__device__ __nv_bfloat16  g_a0 [N_ROWS * DIM];   // bf16 hi split
__device__ __nv_bfloat16  g_a1 [N_ROWS * DIM];   // bf16 lo split
__device__ int            g_ambig[N_ROWS];
__device__ int            g_list [N_ROWS];
__device__ int            g_cnt;

// ---------------------------------------------------------------------------
// Kernel 1: emb = normalize( relu(f*W1)*W2 ).  Bit-matches reference (vec2
// leaf + warp shfl_down tree + warp0 tree). Also emits bf16 hi/lo split and
// resets the ambiguous-row counter.
// ---------------------------------------------------------------------------
__global__ __launch_bounds__(256) void embed_kernel(
    const float* __restrict__ f,
    const float* __restrict__ w1,
    const float* __restrict__ w2)
{
    const int row  = blockIdx.x;
    const int t    = threadIdx.x;
    const int lane = t & 31;
    const int warp = t >> 5;

    if (row == 0 && t == 0) g_cnt = 0;

    const float2 v = reinterpret_cast<const float2*>(f + (size_t)row * DIM)[t];
    const float2 a = reinterpret_cast<const float2*>(w1)[t];
    const float2 b = reinterpret_cast<const float2*>(w2)[t];

    float h0 = __fmul_rn(fmaxf(__fmul_rn(v.x, a.x), 0.0f), b.x);
    float h1 = __fmul_rn(fmaxf(__fmul_rn(v.y, a.y), 0.0f), b.y);

    float acc = __fadd_rn(__fmul_rn(h0, h0), __fmul_rn(h1, h1));

    #pragma unroll
    for (int off = 16; off > 0; off >>= 1)
        acc = __fadd_rn(acc, __shfl_down_sync(0xFFFFFFFFu, acc, off));

    __shared__ float s_w[8];
    __shared__ float s_nrm;
    if (lane == 0) s_w[warp] = acc;
    __syncthreads();

    if (warp == 0) {
        float x = (lane < 8) ? s_w[lane] : 0.0f;
        #pragma unroll
        for (int off = 16; off > 0; off >>= 1)
            x = __fadd_rn(x, __shfl_down_sync(0xFFFFFFFFu, x, off));
        if (lane == 0)
            s_nrm = fmaxf(__fsqrt_rn(x), 1e-12f);
    }
    __syncthreads();

    const float nrm = s_nrm;
    float ox = __fdiv_rn(h0, nrm);
    float oy = __fdiv_rn(h1, nrm);
    reinterpret_cast<float2*>(g_emb + (size_t)row * DIM)[t] =
        make_float2(ox, oy);

    // bf16 hi/lo split.
    __nv_bfloat16 h0x = __float2bfloat16_rn(ox);
    __nv_bfloat16 h0y = __float2bfloat16_rn(oy);
    float rx = __fsub_rn(ox, __bfloat162float(h0x));
    float ry = __fsub_rn(oy, __bfloat162float(h0y));
    __nv_bfloat162 p0; p0.x = h0x; p0.y = h0y;
    __nv_bfloat162 p1; p1.x = __float2bfloat16_rn(rx);
    p1.y = __float2bfloat16_rn(ry);
    reinterpret_cast<__nv_bfloat162*>(g_a0 + (size_t)row * DIM)[t] = p0;
    reinterpret_cast<__nv_bfloat162*>(g_a1 + (size_t)row * DIM)[t] = p1;
}

// ---------------------------------------------------------------------------
// Kernel 2: FAST C = E*E^T via wmma bf16 (4 split passes: a0b0,a1b0,a0b1,a1b1)
// 128x128 CTA tile, 8 warps (2x4), warp tile 64x32, k 16 per step,
// 2-stage cp.async pipeline. Triangle grid + mirror store.
// ---------------------------------------------------------------------------
#define NB   (N_ROWS / 128)
#define NTRI (NB * (NB + 1) / 2)
#define LDT  24   // smem tile pitch in bf16 (48B: LDSM conflict-free, 16B aligned)

__device__ __forceinline__ void cp16(void* sdst, const void* gsrc) {
    unsigned sa = (unsigned)__cvta_generic_to_shared(sdst);
    asm volatile("cp.async.ca.shared.global [%0], [%1], 16;" :: "r"(sa), "l"(gsrc));
}

__global__ __launch_bounds__(256) void gemm_fast(float* __restrict__ C)
{
    const int t5 = blockIdx.x;
    int by = (int)((2.0 * NB + 1.0 - sqrt((2.0 * NB + 1.0) * (2.0 * NB + 1.0)
                                          - 8.0 * (double)t5)) * 0.5);
    while (by > 0      && (by * NB - (by * (by - 1)) / 2) > t5) by--;
    while (by < NB - 1 && ((by + 1) * NB - ((by + 1) * by) / 2) <= t5) by++;
    const int bx = by + (t5 - (by * NB - (by * (by - 1)) / 2));

    const int rowBase = by * 128;
    const int colBase = bx * 128;

    __shared__ __nv_bfloat16 As[2][128][LDT];
    __shared__ __nv_bfloat16 Bs[2][128][LDT];

    const int tid   = threadIdx.x;
    const int wid   = tid >> 5;
    const int warpM = wid & 1;    // 0..1 (64 rows each)
    const int warpN = wid >> 1;   // 0..3 (32 cols each)
    const int lrow  = tid >> 1;
    const int half  = tid & 1;

    wmma::fragment<wmma::accumulator, 16, 16, 16, float> c[4][2];
    #pragma unroll
    for (int i = 0; i < 4; i++)
        #pragma unroll
        for (int j = 0; j < 2; j++)
            wmma::fill_fragment(c[i][j], 0.0f);

    // Issue cp.async loads for step s into buffer buf.
    auto issue = [&](int buf, int s) {
        const int p  = s >> 5;            // pass 0..3
        const int k0 = (s & 31) << 4;     // k offset within E
        const __nv_bfloat16* Aa = (p & 1) ? g_a1 : g_a0;
        const __nv_bfloat16* Bb = (p & 2) ? g_a1 : g_a0;
        cp16(&As[buf][lrow][half * 8],
             Aa + (size_t)(rowBase + lrow) * DIM + k0 + half * 8);
        cp16(&Bs[buf][lrow][half * 8],
             Bb + (size_t)(colBase + lrow) * DIM + k0 + half * 8);
        asm volatile("cp.async.commit_group;");
    };

    issue(0, 0);
    for (int s = 0; s < 128; s++) {
        if (s + 1 < 128) {
            issue((s + 1) & 1, s + 1);
            asm volatile("cp.async.wait_group 1;");
        } else {
            asm volatile("cp.async.wait_group 0;");
        }
        __syncthreads();

        const int b = s & 1;
        wmma::fragment<wmma::matrix_b, 16, 16, 16, __nv_bfloat16,
                       wmma::col_major> bf[2];
        #pragma unroll
        for (int j = 0; j < 2; j++)
            wmma::load_matrix_sync(bf[j], &Bs[b][warpN * 32 + j * 16][0], LDT);
        #pragma unroll
        for (int i = 0; i < 4; i++) {
            wmma::fragment<wmma::matrix_a, 16, 16, 16, __nv_bfloat16,
                           wmma::row_major> af;
            wmma::load_matrix_sync(af, &As[b][warpM * 64 + i * 16][0], LDT);
            #pragma unroll
            for (int j = 0; j < 2; j++)
                wmma::mma_sync(c[i][j], af, bf[j], c[i][j]);
        }
        __syncthreads();
    }

    #pragma unroll
    for (int i = 0; i < 4; i++)
        #pragma unroll
        for (int j = 0; j < 2; j++) {
            const int r0 = rowBase + warpM * 64 + i * 16;
            const int c0 = colBase + warpN * 32 + j * 16;
            wmma::store_matrix_sync(C + (size_t)r0 * N_ROWS + c0, c[i][j],
                                    N_ROWS, wmma::mem_row_major);
            if (bx != by)
                wmma::store_matrix_sync(C + (size_t)c0 * N_ROWS + r0, c[i][j],
                                        N_ROWS, wmma::mem_col_major);
        }
}

// ---------------------------------------------------------------------------
// Order-preserving key helpers.
// ---------------------------------------------------------------------------
__device__ __forceinline__ unsigned f2key(float v) {
    unsigned u = __float_as_uint(v);
    return (u & 0x80000000u) ? ~u : (u | 0x80000000u);
}
__device__ __forceinline__ float key2f(unsigned k) {
    unsigned u = (k & 0x80000000u) ? (k & 0x7FFFFFFFu) : ~k;
    return __uint_as_float(u);
}

// ---------------------------------------------------------------------------
// Kernel 3 (phase A): per-row radix select on FAST sims; if the selection is
// certified (gap >= margin, exactly 31 kept), write masked output. Else mark
// row ambiguous for exact recompute.
// ---------------------------------------------------------------------------
__global__ __launch_bounds__(256) void topk_select(float* __restrict__ C)
{
    __shared__ unsigned keys[N_ROWS];
    __shared__ unsigned hist[256];
    __shared__ unsigned s_prefix;
    __shared__ int      s_rem;
    __shared__ unsigned s_nxt;
    __shared__ int      s_cntge;

    const int row = blockIdx.x;
    const int tid = threadIdx.x;
    float* __restrict__ rowp = C + (size_t)row * N_ROWS;

    for (int i = tid; i < N_ROWS; i += 256)
        keys[i] = f2key(rowp[i]);
    if (tid == 0) { s_nxt = f2key(0.0f); s_cntge = 0; }
    __syncthreads();

    unsigned prefix = 0;
    int remaining = KSEL;

    #pragma unroll
    for (int shift = 24; shift >= 0; shift -= 8) {
        hist[tid] = 0;
        __syncthreads();
        const unsigned himask = (shift == 24) ? 0u : (0xFFFFFFFFu << (shift + 8));
        for (int i = tid; i < N_ROWS; i += 256) {
            const unsigned k = keys[i];
            if ((k & himask) == prefix)
                atomicAdd(&hist[(k >> shift) & 255u], 1u);
        }
        __syncthreads();
        if (tid == 0) {
            int cum = 0, b = 255;
            for (; b >= 0; b--) {
                cum += (int)hist[b];
                if (cum >= remaining) break;
            }
            if (b < 0) b = 0;
            s_prefix = prefix | ((unsigned)b << shift);
            s_rem    = remaining - (cum - (int)hist[b]);
        }
        __syncthreads();
        prefix    = s_prefix;
        remaining = s_rem;
        __syncthreads();
    }

    // Gap + exact-count pass.
    unsigned lmax = f2key(0.0f);
    int lcnt = 0;
    for (int i = tid; i < N_ROWS; i += 256) {
        const unsigned k = keys[i];
        if (k >= prefix) lcnt++;
        else if (k > lmax) lmax = k;
    }
    atomicAdd(&s_cntge, lcnt);
    atomicMax(&s_nxt, lmax);
    __syncthreads();

    const float thrv   = key2f(prefix);
    const float gap    = __fsub_rn(thrv, key2f(s_nxt));
    const float margin = __fmaf_rn(3.2e-5f, thrv, 1.5e-6f);
    const bool  good   = (s_cntge == KSEL) && (gap >= margin);

    if (good) {
        if (tid == 0) g_ambig[row] = 0;
        for (int i = tid; i < N_ROWS; i += 256) {
            const unsigned k = keys[i];
            rowp[i] = (k >= prefix) ? fmaxf(key2f(k), 0.0f) : 0.0f;
        }
    } else {
        if (tid == 0) {
            g_ambig[row] = 1;
            int p = atomicAdd(&g_cnt, 1);
            g_list[p] = row;
        }
    }
}

// ---------------------------------------------------------------------------
// Kernel 4 (phase B): recompute ambiguous rows' sims with the bit-exact
// ascending-k single-accumulator fp32 FMA chain (identical to reference).
// CTA tile: 32 gathered rows x 128 cols, k chunks of 64.
// ---------------------------------------------------------------------------
__global__ __launch_bounds__(256) void gemm_exact(float* __restrict__ C)
{
    const int cnt = g_cnt;
    const int rt  = blockIdx.y;
    if (rt * 32 >= cnt) return;
    const int colBase = blockIdx.x * 128;

    __shared__ int   ids[32];
    __shared__ float Af[32][68];
    __shared__ float Bf[64][132];

    const int tid = threadIdx.x;
    if (tid < 32) {
        int idx = rt * 32 + tid;
        ids[tid] = (idx < cnt) ? g_list[idx] : -1;
    }
    __syncthreads();

    const int rg = tid >> 5;   // 0..7  -> rows rg*4..+3
    const int cg = tid & 31;   // 0..31 -> cols cg*4..+3

    float acc[4][4];
    #pragma unroll
    for (int i = 0; i < 4; i++)
        #pragma unroll
        for (int j = 0; j < 4; j++)
            acc[i][j] = 0.0f;

    for (int kc = 0; kc < DIM; kc += 64) {
        // Load A (gathered ambiguous rows): 32x64 f32 = 512 float4.
        #pragma unroll
        for (int l = 0; l < 2; l++) {
            const int idx = tid + l * 256;
            const int r   = idx >> 4;
            const int c4  = idx & 15;
            const int gid = ids[r];
            float4 v = make_float4(0.f, 0.f, 0.f, 0.f);
            if (gid >= 0)
                v = *reinterpret_cast<const float4*>(
                        &g_emb[(size_t)gid * DIM + kc + c4 * 4]);
            *reinterpret_cast<float4*>(&Af[r][c4 * 4]) = v;
        }
        // Load B (transposed to [k][col]): 128x64 f32 = 2048 float4.
        #pragma unroll
        for (int l = 0; l < 8; l++) {
            const int idx = tid + l * 256;
            const int col = idx >> 4;
            const int c4  = idx & 15;
            float4 v = *reinterpret_cast<const float4*>(
                &g_emb[(size_t)(colBase + col) * DIM + kc + c4 * 4]);
            Bf[c4 * 4 + 0][col] = v.x;
            Bf[c4 * 4 + 1][col] = v.y;
            Bf[c4 * 4 + 2][col] = v.z;
            Bf[c4 * 4 + 3][col] = v.w;
        }
        __syncthreads();

        for (int k = 0; k < 64; k++) {   // ascending k, single accumulator
            float ar[4];
            #pragma unroll
            for (int i = 0; i < 4; i++) ar[i] = Af[rg * 4 + i][k];
            float4 br = *reinterpret_cast<const float4*>(&Bf[k][cg * 4]);
            #pragma unroll
            for (int i = 0; i < 4; i++) {
                acc[i][0] = __fmaf_rn(ar[i], br.x, acc[i][0]);
                acc[i][1] = __fmaf_rn(ar[i], br.y, acc[i][1]);
                acc[i][2] = __fmaf_rn(ar[i], br.z, acc[i][2]);
                acc[i][3] = __fmaf_rn(ar[i], br.w, acc[i][3]);
            }
        }
        __syncthreads();
    }

    #pragma unroll
    for (int i = 0; i < 4; i++) {
        const int gid = ids[rg * 4 + i];
        if (gid >= 0)
            *reinterpret_cast<float4*>(
                &C[(size_t)gid * N_ROWS + colBase + cg * 4]) =
                make_float4(acc[i][0], acc[i][1], acc[i][2], acc[i][3]);
    }
}

// ---------------------------------------------------------------------------
// Kernel 5 (phase C): exact top-k (with jax tie-break) on ambiguous rows only.
// ---------------------------------------------------------------------------
#define MAX_TIES 64

__global__ __launch_bounds__(256) void topk_final(float* __restrict__ C)
{
    const int row = blockIdx.x;
    if (!g_ambig[row]) return;

    __shared__ unsigned keys[N_ROWS];
    __shared__ unsigned hist[256];
    __shared__ unsigned s_prefix;
    __shared__ int      s_rem;
    __shared__ int      eq_idx[MAX_TIES];
    __shared__ int      eq_n;

    const int tid = threadIdx.x;
    float* __restrict__ rowp = C + (size_t)row * N_ROWS;

    for (int i = tid; i < N_ROWS; i += 256)
        keys[i] = f2key(rowp[i]);
    if (tid == 0) eq_n = 0;
    __syncthreads();

    unsigned prefix = 0;
    int remaining = KSEL;

    #pragma unroll
    for (int shift = 24; shift >= 0; shift -= 8) {
        hist[tid] = 0;
        __syncthreads();
        const unsigned himask = (shift == 24) ? 0u : (0xFFFFFFFFu << (shift + 8));
        for (int i = tid; i < N_ROWS; i += 256) {
            const unsigned k = keys[i];
            if ((k & himask) == prefix)
                atomicAdd(&hist[(k >> shift) & 255u], 1u);
        }
        __syncthreads();
        if (tid == 0) {
            int cum = 0, b = 255;
            for (; b >= 0; b--) {
                cum += (int)hist[b];
                if (cum >= remaining) break;
            }
            if (b < 0) b = 0;
            s_prefix = prefix | ((unsigned)b << shift);
            s_rem    = remaining - (cum - (int)hist[b]);
        }
        __syncthreads();
        prefix    = s_prefix;
        remaining = s_rem;
        __syncthreads();
    }

    for (int i = tid; i < N_ROWS; i += 256) {
        if (keys[i] == prefix) {
            int p = atomicAdd(&eq_n, 1);
            if (p < MAX_TIES) eq_idx[p] = i;
        }
    }
    __syncthreads();
    const int m = eq_n;

    for (int i = tid; i < N_ROWS; i += 256) {
        const unsigned k = keys[i];
        float out = 0.0f;
        if (k > prefix) {
            out = fmaxf(key2f(k), 0.0f);
        } else if (k == prefix) {
            bool keep;
            if (m <= remaining || m > MAX_TIES) {
                keep = true;
            } else {
                int r = 0;
                for (int j = 0; j < m; j++) r += (eq_idx[j] < i);
                keep = (r < remaining);
            }
            if (keep) out = fmaxf(key2f(k), 0.0f);
        }
        rowp[i] = out;
    }
}

// ---------------------------------------------------------------------------
extern "C" void kernel_launch(void* const* d_in, const int* in_sizes, int n_in,
                              void* d_out, int out_size)
{
    const float* features = (const float*)d_in[0];  // [8192, 512]
    const float* W1       = (const float*)d_in[1];  // [512]
    const float* W2       = (const float*)d_in[2];  // [512]
    float* out            = (float*)d_out;          // [8192, 8192]

    embed_kernel<<<N_ROWS, 256>>>(features, W1, W2);
    gemm_fast<<<NTRI, 256>>>(out);
    topk_select<<<N_ROWS, 256>>>(out);
    gemm_exact<<<dim3(64, 256), 256>>>(out);
    topk_final<<<N_ROWS, 256>>>(out);
}

// round 9
// speedup vs baseline: 1.3692x; 1.3692x over previous
#include <cuda_runtime.h>
#include <cuda_bf16.h>
#include <mma.h>
#include <cstdint>

using namespace nvcuda;

#define N_ROWS 8192
#define DIM    512
#define KSEL   31   // k+1 entries kept per row

// Scratch (static device arrays; no allocs allowed).
__device__ float          g_emb[N_ROWS * DIM];   // exact fp32 normalized emb
__device__ __nv_bfloat16  g_a0 [N_ROWS * DIM];   // bf16 hi split
__device__ __nv_bfloat16  g_a1 [N_ROWS * DIM];   // bf16 lo split
__device__ int            g_ambig[N_ROWS];
__device__ int            g_list [N_ROWS];
__device__ int            g_cnt;

// ---------------------------------------------------------------------------
// Kernel 1: emb = normalize( relu(f*W1)*W2 ).  Bit-matches reference (vec2
// leaf + warp shfl_down tree + warp0 tree). Emits bf16 hi/lo split too.
// ---------------------------------------------------------------------------
__global__ __launch_bounds__(256) void embed_kernel(
    const float* __restrict__ f,
    const float* __restrict__ w1,
    const float* __restrict__ w2)
{
    const int row  = blockIdx.x;
    const int t    = threadIdx.x;
    const int lane = t & 31;
    const int warp = t >> 5;

    if (row == 0 && t == 0) g_cnt = 0;

    const float2 v = reinterpret_cast<const float2*>(f + (size_t)row * DIM)[t];
    const float2 a = reinterpret_cast<const float2*>(w1)[t];
    const float2 b = reinterpret_cast<const float2*>(w2)[t];

    float h0 = __fmul_rn(fmaxf(__fmul_rn(v.x, a.x), 0.0f), b.x);
    float h1 = __fmul_rn(fmaxf(__fmul_rn(v.y, a.y), 0.0f), b.y);

    float acc = __fadd_rn(__fmul_rn(h0, h0), __fmul_rn(h1, h1));

    #pragma unroll
    for (int off = 16; off > 0; off >>= 1)
        acc = __fadd_rn(acc, __shfl_down_sync(0xFFFFFFFFu, acc, off));

    __shared__ float s_w[8];
    __shared__ float s_nrm;
    if (lane == 0) s_w[warp] = acc;
    __syncthreads();

    if (warp == 0) {
        float x = (lane < 8) ? s_w[lane] : 0.0f;
        #pragma unroll
        for (int off = 16; off > 0; off >>= 1)
            x = __fadd_rn(x, __shfl_down_sync(0xFFFFFFFFu, x, off));
        if (lane == 0)
            s_nrm = fmaxf(__fsqrt_rn(x), 1e-12f);
    }
    __syncthreads();

    const float nrm = s_nrm;
    float ox = __fdiv_rn(h0, nrm);
    float oy = __fdiv_rn(h1, nrm);
    reinterpret_cast<float2*>(g_emb + (size_t)row * DIM)[t] =
        make_float2(ox, oy);

    __nv_bfloat16 h0x = __float2bfloat16_rn(ox);
    __nv_bfloat16 h0y = __float2bfloat16_rn(oy);
    float rx = __fsub_rn(ox, __bfloat162float(h0x));
    float ry = __fsub_rn(oy, __bfloat162float(h0y));
    __nv_bfloat162 p0; p0.x = h0x; p0.y = h0y;
    __nv_bfloat162 p1; p1.x = __float2bfloat16_rn(rx);
    p1.y = __float2bfloat16_rn(ry);
    reinterpret_cast<__nv_bfloat162*>(g_a0 + (size_t)row * DIM)[t] = p0;
    reinterpret_cast<__nv_bfloat162*>(g_a1 + (size_t)row * DIM)[t] = p1;
}

// ---------------------------------------------------------------------------
// Kernel 2: FAST C = E*E^T via wmma bf16, 3 fused split passes per k-chunk:
//   c += A0*B0 + A1*B0 + A0*B1      (A1*B1 dropped; covered by margin)
// 128x128 CTA tile, 8 warps (2x4), warp tile 64x32. Double-buffered cp.async
// stages of k=16 carrying all 4 tiles (a0r,a1r,a0c,a1c). Triangle grid;
// direct wmma mirror store (tile region stays L2-resident -> coalesces).
// ---------------------------------------------------------------------------
#define NB   (N_ROWS / 128)
#define NTRI (NB * (NB + 1) / 2)
#define LDT  24   // 48B pitch: 16B-aligned rows, ldmatrix conflict-free

__device__ __forceinline__ void cp16(void* sdst, const void* gsrc) {
    unsigned sa = (unsigned)__cvta_generic_to_shared(sdst);
    asm volatile("cp.async.ca.shared.global [%0], [%1], 16;" :: "r"(sa), "l"(gsrc));
}

__global__ __launch_bounds__(256) void gemm_fast(float* __restrict__ C)
{
    const int t5 = blockIdx.x;
    int by = (int)((2.0 * NB + 1.0 - sqrt((2.0 * NB + 1.0) * (2.0 * NB + 1.0)
                                          - 8.0 * (double)t5)) * 0.5);
    while (by > 0      && (by * NB - (by * (by - 1)) / 2) > t5) by--;
    while (by < NB - 1 && ((by + 1) * NB - ((by + 1) * by) / 2) <= t5) by++;
    const int bx = by + (t5 - (by * NB - (by * (by - 1)) / 2));

    const int rowBase = by * 128;
    const int colBase = bx * 128;

    // 2 bufs x 4 tiles x 128 x LDT bf16 = 48KB exactly.
    __shared__ __nv_bfloat16 sA0[2][128][LDT];
    __shared__ __nv_bfloat16 sA1[2][128][LDT];
    __shared__ __nv_bfloat16 sB0[2][128][LDT];
    __shared__ __nv_bfloat16 sB1[2][128][LDT];

    const int tid   = threadIdx.x;
    const int wid   = tid >> 5;
    const int warpM = wid & 1;    // 0..1 (64 rows)
    const int warpN = wid >> 1;   // 0..3 (32 cols)
    const int lrow  = tid >> 1;   // 0..127
    const int half  = tid & 1;    // 16B half of the 32B k-slice

    wmma::fragment<wmma::accumulator, 16, 16, 16, float> c[4][2];
    #pragma unroll
    for (int i = 0; i < 4; i++)
        #pragma unroll
        for (int j = 0; j < 2; j++)
            wmma::fill_fragment(c[i][j], 0.0f);

    const size_t rOff = (size_t)(rowBase + lrow) * DIM + half * 8;
    const size_t cOff = (size_t)(colBase + lrow) * DIM + half * 8;

    auto issue = [&](int buf, int s) {
        const int k0 = s << 4;
        cp16(&sA0[buf][lrow][half * 8], g_a0 + rOff + k0);
        cp16(&sA1[buf][lrow][half * 8], g_a1 + rOff + k0);
        cp16(&sB0[buf][lrow][half * 8], g_a0 + cOff + k0);
        cp16(&sB1[buf][lrow][half * 8], g_a1 + cOff + k0);
        asm volatile("cp.async.commit_group;");
    };

    const int NSTAGE = DIM / 16;   // 32
    issue(0, 0);
    issue(1, 1);

    for (int s = 0; s < NSTAGE; s++) {
        if (s + 2 < NSTAGE) asm volatile("cp.async.wait_group 1;");
        else                asm volatile("cp.async.wait_group 0;");
        __syncthreads();

        const int b = s & 1;
        wmma::fragment<wmma::matrix_a, 16, 16, 16, __nv_bfloat16,
                       wmma::row_major> a0f[4], a1f[4];
        wmma::fragment<wmma::matrix_b, 16, 16, 16, __nv_bfloat16,
                       wmma::col_major> b0f[2], b1f[2];
        #pragma unroll
        for (int i = 0; i < 4; i++) {
            wmma::load_matrix_sync(a0f[i], &sA0[b][warpM * 64 + i * 16][0], LDT);
            wmma::load_matrix_sync(a1f[i], &sA1[b][warpM * 64 + i * 16][0], LDT);
        }
        #pragma unroll
        for (int j = 0; j < 2; j++) {
            wmma::load_matrix_sync(b0f[j], &sB0[b][warpN * 32 + j * 16][0], LDT);
            wmma::load_matrix_sync(b1f[j], &sB1[b][warpN * 32 + j * 16][0], LDT);
        }
        #pragma unroll
        for (int i = 0; i < 4; i++)
            #pragma unroll
            for (int j = 0; j < 2; j++) {
                wmma::mma_sync(c[i][j], a0f[i], b0f[j], c[i][j]);
                wmma::mma_sync(c[i][j], a1f[i], b0f[j], c[i][j]);
                wmma::mma_sync(c[i][j], a0f[i], b1f[j], c[i][j]);
            }
        __syncthreads();   // protect buffer b before reissue
        if (s + 2 < NSTAGE) issue(b, s + 2);
    }

    #pragma unroll
    for (int i = 0; i < 4; i++)
        #pragma unroll
        for (int j = 0; j < 2; j++) {
            const int r0 = rowBase + warpM * 64 + i * 16;
            const int c0 = colBase + warpN * 32 + j * 16;
            wmma::store_matrix_sync(C + (size_t)r0 * N_ROWS + c0, c[i][j],
                                    N_ROWS, wmma::mem_row_major);
            if (bx != by)
                wmma::store_matrix_sync(C + (size_t)c0 * N_ROWS + r0, c[i][j],
                                        N_ROWS, wmma::mem_col_major);
        }
}

// ---------------------------------------------------------------------------
__device__ __forceinline__ unsigned f2key(float v) {
    unsigned u = __float_as_uint(v);
    return (u & 0x80000000u) ? ~u : (u | 0x80000000u);
}
__device__ __forceinline__ float key2f(unsigned k) {
    unsigned u = (k & 0x80000000u) ? (k & 0x7FFFFFFFu) : ~k;
    return __uint_as_float(u);
}

// ---------------------------------------------------------------------------
// Kernel 3 (phase A): radix select on FAST sims; certify or mark ambiguous.
// ---------------------------------------------------------------------------
__global__ __launch_bounds__(256) void topk_select(float* __restrict__ C)
{
    __shared__ unsigned keys[N_ROWS];
    __shared__ unsigned hist[256];
    __shared__ unsigned s_prefix;
    __shared__ int      s_rem;
    __shared__ unsigned s_nxt;
    __shared__ int      s_cntge;

    const int row = blockIdx.x;
    const int tid = threadIdx.x;
    float* __restrict__ rowp = C + (size_t)row * N_ROWS;

    for (int i = tid; i < N_ROWS; i += 256)
        keys[i] = f2key(rowp[i]);
    if (tid == 0) { s_nxt = f2key(0.0f); s_cntge = 0; }
    __syncthreads();

    unsigned prefix = 0;
    int remaining = KSEL;

    #pragma unroll
    for (int shift = 24; shift >= 0; shift -= 8) {
        hist[tid] = 0;
        __syncthreads();
        const unsigned himask = (shift == 24) ? 0u : (0xFFFFFFFFu << (shift + 8));
        for (int i = tid; i < N_ROWS; i += 256) {
            const unsigned k = keys[i];
            if ((k & himask) == prefix)
                atomicAdd(&hist[(k >> shift) & 255u], 1u);
        }
        __syncthreads();
        if (tid == 0) {
            int cum = 0, b = 255;
            for (; b >= 0; b--) {
                cum += (int)hist[b];
                if (cum >= remaining) break;
            }
            if (b < 0) b = 0;
            s_prefix = prefix | ((unsigned)b << shift);
            s_rem    = remaining - (cum - (int)hist[b]);
        }
        __syncthreads();
        prefix    = s_prefix;
        remaining = s_rem;
        __syncthreads();
    }

    unsigned lmax = f2key(0.0f);
    int lcnt = 0;
    for (int i = tid; i < N_ROWS; i += 256) {
        const unsigned k = keys[i];
        if (k >= prefix) lcnt++;
        else if (k > lmax) lmax = k;
    }
    atomicAdd(&s_cntge, lcnt);
    atomicMax(&s_nxt, lmax);
    __syncthreads();

    const float thrv   = key2f(prefix);
    const float gap    = __fsub_rn(thrv, key2f(s_nxt));
    const float margin = __fmaf_rn(4.2e-5f, thrv, 2.0e-6f);
    const bool  good   = (s_cntge == KSEL) && (gap >= margin);

    if (good) {
        if (tid == 0) g_ambig[row] = 0;
        for (int i = tid; i < N_ROWS; i += 256) {
            const unsigned k = keys[i];
            rowp[i] = (k >= prefix) ? fmaxf(key2f(k), 0.0f) : 0.0f;
        }
    } else {
        if (tid == 0) {
            g_ambig[row] = 1;
            int p = atomicAdd(&g_cnt, 1);
            g_list[p] = row;
        }
    }
}

// ---------------------------------------------------------------------------
// Kernel 4 (phase B): exact sims for ambiguous rows (bit-identical ascending-k
// fp32 FMA chain). Persistent over row-tiles: grid (64, 8).
// ---------------------------------------------------------------------------
__global__ __launch_bounds__(256) void gemm_exact(float* __restrict__ C)
{
    const int cnt = g_cnt;
    const int colBase = blockIdx.x * 128;

    for (int rt = blockIdx.y; rt * 32 < cnt; rt += 8) {
        __shared__ int   ids[32];
        __shared__ float Af[32][68];
        __shared__ float Bf[64][132];

        const int tid = threadIdx.x;
        __syncthreads();   // reuse guard across rt iterations
        if (tid < 32) {
            int idx = rt * 32 + tid;
            ids[tid] = (idx < cnt) ? g_list[idx] : -1;
        }
        __syncthreads();

        const int rg = tid >> 5;
        const int cg = tid & 31;

        float acc[4][4];
        #pragma unroll
        for (int i = 0; i < 4; i++)
            #pragma unroll
            for (int j = 0; j < 4; j++)
                acc[i][j] = 0.0f;

        for (int kc = 0; kc < DIM; kc += 64) {
            #pragma unroll
            for (int l = 0; l < 2; l++) {
                const int idx = tid + l * 256;
                const int r   = idx >> 4;
                const int c4  = idx & 15;
                const int gid = ids[r];
                float4 v = make_float4(0.f, 0.f, 0.f, 0.f);
                if (gid >= 0)
                    v = *reinterpret_cast<const float4*>(
                            &g_emb[(size_t)gid * DIM + kc + c4 * 4]);
                *reinterpret_cast<float4*>(&Af[r][c4 * 4]) = v;
            }
            #pragma unroll
            for (int l = 0; l < 8; l++) {
                const int idx = tid + l * 256;
                const int col = idx >> 4;
                const int c4  = idx & 15;
                float4 v = *reinterpret_cast<const float4*>(
                    &g_emb[(size_t)(colBase + col) * DIM + kc + c4 * 4]);
                Bf[c4 * 4 + 0][col] = v.x;
                Bf[c4 * 4 + 1][col] = v.y;
                Bf[c4 * 4 + 2][col] = v.z;
                Bf[c4 * 4 + 3][col] = v.w;
            }
            __syncthreads();

            for (int k = 0; k < 64; k++) {
                float ar[4];
                #pragma unroll
                for (int i = 0; i < 4; i++) ar[i] = Af[rg * 4 + i][k];
                float4 br = *reinterpret_cast<const float4*>(&Bf[k][cg * 4]);
                #pragma unroll
                for (int i = 0; i < 4; i++) {
                    acc[i][0] = __fmaf_rn(ar[i], br.x, acc[i][0]);
                    acc[i][1] = __fmaf_rn(ar[i], br.y, acc[i][1]);
                    acc[i][2] = __fmaf_rn(ar[i], br.z, acc[i][2]);
                    acc[i][3] = __fmaf_rn(ar[i], br.w, acc[i][3]);
                }
            }
            __syncthreads();
        }

        #pragma unroll
        for (int i = 0; i < 4; i++) {
            const int gid = ids[rg * 4 + i];
            if (gid >= 0)
                *reinterpret_cast<float4*>(
                    &C[(size_t)gid * N_ROWS + colBase + cg * 4]) =
                    make_float4(acc[i][0], acc[i][1], acc[i][2], acc[i][3]);
        }
    }
}

// ---------------------------------------------------------------------------
// Kernel 5 (phase C): exact top-k (jax tie-break) on ambiguous rows only.
// ---------------------------------------------------------------------------
#define MAX_TIES 64

__global__ __launch_bounds__(256) void topk_final(float* __restrict__ C)
{
    const int row = blockIdx.x;
    if (!g_ambig[row]) return;

    __shared__ unsigned keys[N_ROWS];
    __shared__ unsigned hist[256];
    __shared__ unsigned s_prefix;
    __shared__ int      s_rem;
    __shared__ int      eq_idx[MAX_TIES];
    __shared__ int      eq_n;

    const int tid = threadIdx.x;
    float* __restrict__ rowp = C + (size_t)row * N_ROWS;

    for (int i = tid; i < N_ROWS; i += 256)
        keys[i] = f2key(rowp[i]);
    if (tid == 0) eq_n = 0;
    __syncthreads();

    unsigned prefix = 0;
    int remaining = KSEL;

    #pragma unroll
    for (int shift = 24; shift >= 0; shift -= 8) {
        hist[tid] = 0;
        __syncthreads();
        const unsigned himask = (shift == 24) ? 0u : (0xFFFFFFFFu << (shift + 8));
        for (int i = tid; i < N_ROWS; i += 256) {
            const unsigned k = keys[i];
            if ((k & himask) == prefix)
                atomicAdd(&hist[(k >> shift) & 255u], 1u);
        }
        __syncthreads();
        if (tid == 0) {
            int cum = 0, b = 255;
            for (; b >= 0; b--) {
                cum += (int)hist[b];
                if (cum >= remaining) break;
            }
            if (b < 0) b = 0;
            s_prefix = prefix | ((unsigned)b << shift);
            s_rem    = remaining - (cum - (int)hist[b]);
        }
        __syncthreads();
        prefix    = s_prefix;
        remaining = s_rem;
        __syncthreads();
    }

    for (int i = tid; i < N_ROWS; i += 256) {
        if (keys[i] == prefix) {
            int p = atomicAdd(&eq_n, 1);
            if (p < MAX_TIES) eq_idx[p] = i;
        }
    }
    __syncthreads();
    const int m = eq_n;

    for (int i = tid; i < N_ROWS; i += 256) {
        const unsigned k = keys[i];
        float out = 0.0f;
        if (k > prefix) {
            out = fmaxf(key2f(k), 0.0f);
        } else if (k == prefix) {
            bool keep;
            if (m <= remaining || m > MAX_TIES) {
                keep = true;
            } else {
                int r = 0;
                for (int j = 0; j < m; j++) r += (eq_idx[j] < i);
                keep = (r < remaining);
            }
            if (keep) out = fmaxf(key2f(k), 0.0f);
        }
        rowp[i] = out;
    }
}

// ---------------------------------------------------------------------------
extern "C" void kernel_launch(void* const* d_in, const int* in_sizes, int n_in,
                              void* d_out, int out_size)
{
    const float* features = (const float*)d_in[0];  // [8192, 512]
    const float* W1       = (const float*)d_in[1];  // [512]
    const float* W2       = (const float*)d_in[2];  // [512]
    float* out            = (float*)d_out;          // [8192, 8192]

    embed_kernel<<<N_ROWS, 256>>>(features, W1, W2);
    gemm_fast<<<NTRI, 256>>>(out);
    topk_select<<<N_ROWS, 256>>>(out);
    gemm_exact<<<dim3(64, 8), 256>>>(out);
    topk_final<<<N_ROWS, 256>>>(out);
}

// round 10
// speedup vs baseline: 1.6194x; 1.1827x over previous
#include <cuda_runtime.h>
#include <cuda_fp16.h>
#include <mma.h>
#include <cstdint>

using namespace nvcuda;

#define N_ROWS 8192
#define DIM    512
#define KSEL   31   // k+1 entries kept per row

// Scratch (static device arrays; no allocs allowed).
__device__ float   g_emb[N_ROWS * DIM];   // exact fp32 normalized emb
__device__ __half  g_a0 [N_ROWS * DIM];   // fp16 hi split
__device__ __half  g_a1 [N_ROWS * DIM];   // fp16 lo split
__device__ int     g_ambig[N_ROWS];
__device__ int     g_list [N_ROWS];
__device__ int     g_cnt;

// ---------------------------------------------------------------------------
// Kernel 1: emb = normalize( relu(f*W1)*W2 ).  Bit-matches reference (vec2
// leaf + warp shfl_down tree + warp0 tree). Emits fp16 hi/lo split too.
// ---------------------------------------------------------------------------
__global__ __launch_bounds__(256) void embed_kernel(
    const float* __restrict__ f,
    const float* __restrict__ w1,
    const float* __restrict__ w2)
{
    const int row  = blockIdx.x;
    const int t    = threadIdx.x;
    const int lane = t & 31;
    const int warp = t >> 5;

    if (row == 0 && t == 0) g_cnt = 0;

    const float2 v = reinterpret_cast<const float2*>(f + (size_t)row * DIM)[t];
    const float2 a = reinterpret_cast<const float2*>(w1)[t];
    const float2 b = reinterpret_cast<const float2*>(w2)[t];

    float h0 = __fmul_rn(fmaxf(__fmul_rn(v.x, a.x), 0.0f), b.x);
    float h1 = __fmul_rn(fmaxf(__fmul_rn(v.y, a.y), 0.0f), b.y);

    float acc = __fadd_rn(__fmul_rn(h0, h0), __fmul_rn(h1, h1));

    #pragma unroll
    for (int off = 16; off > 0; off >>= 1)
        acc = __fadd_rn(acc, __shfl_down_sync(0xFFFFFFFFu, acc, off));

    __shared__ float s_w[8];
    __shared__ float s_nrm;
    if (lane == 0) s_w[warp] = acc;
    __syncthreads();

    if (warp == 0) {
        float x = (lane < 8) ? s_w[lane] : 0.0f;
        #pragma unroll
        for (int off = 16; off > 0; off >>= 1)
            x = __fadd_rn(x, __shfl_down_sync(0xFFFFFFFFu, x, off));
        if (lane == 0)
            s_nrm = fmaxf(__fsqrt_rn(x), 1e-12f);
    }
    __syncthreads();

    const float nrm = s_nrm;
    float ox = __fdiv_rn(h0, nrm);
    float oy = __fdiv_rn(h1, nrm);
    reinterpret_cast<float2*>(g_emb + (size_t)row * DIM)[t] =
        make_float2(ox, oy);

    // fp16 hi/lo split.
    __half h0x = __float2half_rn(ox);
    __half h0y = __float2half_rn(oy);
    float rx = __fsub_rn(ox, __half2float(h0x));
    float ry = __fsub_rn(oy, __half2float(h0y));
    __half2 p0; p0.x = h0x; p0.y = h0y;
    __half2 p1; p1.x = __float2half_rn(rx);
    p1.y = __float2half_rn(ry);
    reinterpret_cast<__half2*>(g_a0 + (size_t)row * DIM)[t] = p0;
    reinterpret_cast<__half2*>(g_a1 + (size_t)row * DIM)[t] = p1;
}

// ---------------------------------------------------------------------------
// Kernel 2: FAST C = E*E^T via wmma fp16, 3 fused split passes per k-chunk:
//   c += A0*B0 + A1*B0 + A0*B1      (A1*B1 dropped; covered by margin)
// 128x128 CTA tile, 8 warps (2x4), warp tile 64x32. 3-stage cp.async pipeline
// with ONE __syncthreads per stage. Triangle grid; direct mirror store.
// ---------------------------------------------------------------------------
#define NB   (N_ROWS / 128)
#define NTRI (NB * (NB + 1) / 2)
#define LDT  24   // 48B pitch: 16B-aligned rows, ldmatrix conflict-free
#define NSTAGE (DIM / 16)   // 32

__device__ __forceinline__ void cp16(void* sdst, const void* gsrc) {
    unsigned sa = (unsigned)__cvta_generic_to_shared(sdst);
    asm volatile("cp.async.ca.shared.global [%0], [%1], 16;" :: "r"(sa), "l"(gsrc));
}

__global__ __launch_bounds__(256) void gemm_fast(float* __restrict__ C)
{
    const int t5 = blockIdx.x;
    int by = (int)((2.0 * NB + 1.0 - sqrt((2.0 * NB + 1.0) * (2.0 * NB + 1.0)
                                          - 8.0 * (double)t5)) * 0.5);
    while (by > 0      && (by * NB - (by * (by - 1)) / 2) > t5) by--;
    while (by < NB - 1 && ((by + 1) * NB - ((by + 1) * by) / 2) <= t5) by++;
    const int bx = by + (t5 - (by * NB - (by * (by - 1)) / 2));

    const int rowBase = by * 128;
    const int colBase = bx * 128;

    // 3 bufs x 4 tiles x 128 x LDT halfs = 72KB.
    __shared__ __half sA0[3][128][LDT];
    __shared__ __half sA1[3][128][LDT];
    __shared__ __half sB0[3][128][LDT];
    __shared__ __half sB1[3][128][LDT];

    const int tid   = threadIdx.x;
    const int wid   = tid >> 5;
    const int warpM = wid & 1;    // 0..1 (64 rows)
    const int warpN = wid >> 1;   // 0..3 (32 cols)
    const int lrow  = tid >> 1;   // 0..127
    const int half_ = tid & 1;    // 16B half of the 32B k-slice

    wmma::fragment<wmma::accumulator, 16, 16, 16, float> c[4][2];
    #pragma unroll
    for (int i = 0; i < 4; i++)
        #pragma unroll
        for (int j = 0; j < 2; j++)
            wmma::fill_fragment(c[i][j], 0.0f);

    const size_t rOff = (size_t)(rowBase + lrow) * DIM + half_ * 8;
    const size_t cOff = (size_t)(colBase + lrow) * DIM + half_ * 8;

    auto issue = [&](int buf, int s) {
        const int k0 = s << 4;
        cp16(&sA0[buf][lrow][half_ * 8], g_a0 + rOff + k0);
        cp16(&sA1[buf][lrow][half_ * 8], g_a1 + rOff + k0);
        cp16(&sB0[buf][lrow][half_ * 8], g_a0 + cOff + k0);
        cp16(&sB1[buf][lrow][half_ * 8], g_a1 + cOff + k0);
        asm volatile("cp.async.commit_group;");
    };

    issue(0, 0);
    issue(1, 1);

    for (int s = 0; s < NSTAGE; s++) {
        // Ensure stage s's group is complete (allow stage s+1 in flight).
        if (s + 1 < NSTAGE) asm volatile("cp.async.wait_group 1;");
        else                asm volatile("cp.async.wait_group 0;");
        __syncthreads();   // orders: all reads of buf (s-1)%3 done; buf s%3 visible

        // Prefetch stage s+2 into buf (s+2)%3 (last read at stage s-1).
        if (s + 2 < NSTAGE) issue((s + 2) % 3, s + 2);

        const int b = s % 3;
        wmma::fragment<wmma::matrix_a, 16, 16, 16, __half,
                       wmma::row_major> a0f[4], a1f[4];
        wmma::fragment<wmma::matrix_b, 16, 16, 16, __half,
                       wmma::col_major> b0f[2], b1f[2];
        #pragma unroll
        for (int i = 0; i < 4; i++) {
            wmma::load_matrix_sync(a0f[i], &sA0[b][warpM * 64 + i * 16][0], LDT);
            wmma::load_matrix_sync(a1f[i], &sA1[b][warpM * 64 + i * 16][0], LDT);
        }
        #pragma unroll
        for (int j = 0; j < 2; j++) {
            wmma::load_matrix_sync(b0f[j], &sB0[b][warpN * 32 + j * 16][0], LDT);
            wmma::load_matrix_sync(b1f[j], &sB1[b][warpN * 32 + j * 16][0], LDT);
        }
        #pragma unroll
        for (int i = 0; i < 4; i++)
            #pragma unroll
            for (int j = 0; j < 2; j++) {
                wmma::mma_sync(c[i][j], a0f[i], b0f[j], c[i][j]);
                wmma::mma_sync(c[i][j], a1f[i], b0f[j], c[i][j]);
                wmma::mma_sync(c[i][j], a0f[i], b1f[j], c[i][j]);
            }
    }

    #pragma unroll
    for (int i = 0; i < 4; i++)
        #pragma unroll
        for (int j = 0; j < 2; j++) {
            const int r0 = rowBase + warpM * 64 + i * 16;
            const int c0 = colBase + warpN * 32 + j * 16;
            wmma::store_matrix_sync(C + (size_t)r0 * N_ROWS + c0, c[i][j],
                                    N_ROWS, wmma::mem_row_major);
            if (bx != by)
                wmma::store_matrix_sync(C + (size_t)c0 * N_ROWS + r0, c[i][j],
                                        N_ROWS, wmma::mem_col_major);
        }
}

// ---------------------------------------------------------------------------
__device__ __forceinline__ unsigned f2key(float v) {
    unsigned u = __float_as_uint(v);
    return (u & 0x80000000u) ? ~u : (u | 0x80000000u);
}
__device__ __forceinline__ float key2f(unsigned k) {
    unsigned u = (k & 0x80000000u) ? (k & 0x7FFFFFFFu) : ~k;
    return __uint_as_float(u);
}

// ---------------------------------------------------------------------------
// Kernel 3 (phase A): radix select on FAST sims; certify or mark ambiguous.
// fp16-split error bound: margin = 1.2e-5*thr + 5e-6.
// ---------------------------------------------------------------------------
__global__ __launch_bounds__(256) void topk_select(float* __restrict__ C)
{
    __shared__ unsigned keys[N_ROWS];
    __shared__ unsigned hist[256];
    __shared__ unsigned s_prefix;
    __shared__ int      s_rem;
    __shared__ unsigned s_nxt;
    __shared__ int      s_cntge;

    const int row = blockIdx.x;
    const int tid = threadIdx.x;
    float* __restrict__ rowp = C + (size_t)row * N_ROWS;

    for (int i = tid; i < N_ROWS; i += 256)
        keys[i] = f2key(rowp[i]);
    if (tid == 0) { s_nxt = f2key(0.0f); s_cntge = 0; }
    __syncthreads();

    unsigned prefix = 0;
    int remaining = KSEL;

    #pragma unroll
    for (int shift = 24; shift >= 0; shift -= 8) {
        hist[tid] = 0;
        __syncthreads();
        const unsigned himask = (shift == 24) ? 0u : (0xFFFFFFFFu << (shift + 8));
        for (int i = tid; i < N_ROWS; i += 256) {
            const unsigned k = keys[i];
            if ((k & himask) == prefix)
                atomicAdd(&hist[(k >> shift) & 255u], 1u);
        }
        __syncthreads();
        if (tid == 0) {
            int cum = 0, b = 255;
            for (; b >= 0; b--) {
                cum += (int)hist[b];
                if (cum >= remaining) break;
            }
            if (b < 0) b = 0;
            s_prefix = prefix | ((unsigned)b << shift);
            s_rem    = remaining - (cum - (int)hist[b]);
        }
        __syncthreads();
        prefix    = s_prefix;
        remaining = s_rem;
        __syncthreads();
    }

    unsigned lmax = f2key(0.0f);
    int lcnt = 0;
    for (int i = tid; i < N_ROWS; i += 256) {
        const unsigned k = keys[i];
        if (k >= prefix) lcnt++;
        else if (k > lmax) lmax = k;
    }
    atomicAdd(&s_cntge, lcnt);
    atomicMax(&s_nxt, lmax);
    __syncthreads();

    const float thrv   = key2f(prefix);
    const float gap    = __fsub_rn(thrv, key2f(s_nxt));
    const float margin = __fmaf_rn(1.2e-5f, thrv, 5.0e-6f);
    const bool  good   = (s_cntge == KSEL) && (gap >= margin);

    if (good) {
        if (tid == 0) g_ambig[row] = 0;
        for (int i = tid; i < N_ROWS; i += 256) {
            const unsigned k = keys[i];
            rowp[i] = (k >= prefix) ? fmaxf(key2f(k), 0.0f) : 0.0f;
        }
    } else {
        if (tid == 0) {
            g_ambig[row] = 1;
            int p = atomicAdd(&g_cnt, 1);
            g_list[p] = row;
        }
    }
}

// ---------------------------------------------------------------------------
// Kernel 4 (phase B): exact sims for ambiguous rows (bit-identical ascending-k
// fp32 FMA chain). Persistent over row-tiles: grid (64, 8).
// ---------------------------------------------------------------------------
__global__ __launch_bounds__(256) void gemm_exact(float* __restrict__ C)
{
    const int cnt = g_cnt;
    const int colBase = blockIdx.x * 128;

    for (int rt = blockIdx.y; rt * 32 < cnt; rt += 8) {
        __shared__ int   ids[32];
        __shared__ float Af[32][68];
        __shared__ float Bf[64][132];

        const int tid = threadIdx.x;
        __syncthreads();
        if (tid < 32) {
            int idx = rt * 32 + tid;
            ids[tid] = (idx < cnt) ? g_list[idx] : -1;
        }
        __syncthreads();

        const int rg = tid >> 5;
        const int cg = tid & 31;

        float acc[4][4];
        #pragma unroll
        for (int i = 0; i < 4; i++)
            #pragma unroll
            for (int j = 0; j < 4; j++)
                acc[i][j] = 0.0f;

        for (int kc = 0; kc < DIM; kc += 64) {
            #pragma unroll
            for (int l = 0; l < 2; l++) {
                const int idx = tid + l * 256;
                const int r   = idx >> 4;
                const int c4  = idx & 15;
                const int gid = ids[r];
                float4 v = make_float4(0.f, 0.f, 0.f, 0.f);
                if (gid >= 0)
                    v = *reinterpret_cast<const float4*>(
                            &g_emb[(size_t)gid * DIM + kc + c4 * 4]);
                *reinterpret_cast<float4*>(&Af[r][c4 * 4]) = v;
            }
            #pragma unroll
            for (int l = 0; l < 8; l++) {
                const int idx = tid + l * 256;
                const int col = idx >> 4;
                const int c4  = idx & 15;
                float4 v = *reinterpret_cast<const float4*>(
                    &g_emb[(size_t)(colBase + col) * DIM + kc + c4 * 4]);
                Bf[c4 * 4 + 0][col] = v.x;
                Bf[c4 * 4 + 1][col] = v.y;
                Bf[c4 * 4 + 2][col] = v.z;
                Bf[c4 * 4 + 3][col] = v.w;
            }
            __syncthreads();

            for (int k = 0; k < 64; k++) {
                float ar[4];
                #pragma unroll
                for (int i = 0; i < 4; i++) ar[i] = Af[rg * 4 + i][k];
                float4 br = *reinterpret_cast<const float4*>(&Bf[k][cg * 4]);
                #pragma unroll
                for (int i = 0; i < 4; i++) {
                    acc[i][0] = __fmaf_rn(ar[i], br.x, acc[i][0]);
                    acc[i][1] = __fmaf_rn(ar[i], br.y, acc[i][1]);
                    acc[i][2] = __fmaf_rn(ar[i], br.z, acc[i][2]);
                    acc[i][3] = __fmaf_rn(ar[i], br.w, acc[i][3]);
                }
            }
            __syncthreads();
        }

        #pragma unroll
        for (int i = 0; i < 4; i++) {
            const int gid = ids[rg * 4 + i];
            if (gid >= 0)
                *reinterpret_cast<float4*>(
                    &C[(size_t)gid * N_ROWS + colBase + cg * 4]) =
                    make_float4(acc[i][0], acc[i][1], acc[i][2], acc[i][3]);
        }
    }
}

// ---------------------------------------------------------------------------
// Kernel 5 (phase C): exact top-k (jax tie-break) on ambiguous rows only.
// ---------------------------------------------------------------------------
#define MAX_TIES 64

__global__ __launch_bounds__(256) void topk_final(float* __restrict__ C)
{
    const int row = blockIdx.x;
    if (!g_ambig[row]) return;

    __shared__ unsigned keys[N_ROWS];
    __shared__ unsigned hist[256];
    __shared__ unsigned s_prefix;
    __shared__ int      s_rem;
    __shared__ int      eq_idx[MAX_TIES];
    __shared__ int      eq_n;

    const int tid = threadIdx.x;
    float* __restrict__ rowp = C + (size_t)row * N_ROWS;

    for (int i = tid; i < N_ROWS; i += 256)
        keys[i] = f2key(rowp[i]);
    if (tid == 0) eq_n = 0;
    __syncthreads();

    unsigned prefix = 0;
    int remaining = KSEL;

    #pragma unroll
    for (int shift = 24; shift >= 0; shift -= 8) {
        hist[tid] = 0;
        __syncthreads();
        const unsigned himask = (shift == 24) ? 0u : (0xFFFFFFFFu << (shift + 8));
        for (int i = tid; i < N_ROWS; i += 256) {
            const unsigned k = keys[i];
            if ((k & himask) == prefix)
                atomicAdd(&hist[(k >> shift) & 255u], 1u);
        }
        __syncthreads();
        if (tid == 0) {
            int cum = 0, b = 255;
            for (; b >= 0; b--) {
                cum += (int)hist[b];
                if (cum >= remaining) break;
            }
            if (b < 0) b = 0;
            s_prefix = prefix | ((unsigned)b << shift);
            s_rem    = remaining - (cum - (int)hist[b]);
        }
        __syncthreads();
        prefix    = s_prefix;
        remaining = s_rem;
        __syncthreads();
    }

    for (int i = tid; i < N_ROWS; i += 256) {
        if (keys[i] == prefix) {
            int p = atomicAdd(&eq_n, 1);
            if (p < MAX_TIES) eq_idx[p] = i;
        }
    }
    __syncthreads();
    const int m = eq_n;

    for (int i = tid; i < N_ROWS; i += 256) {
        const unsigned k = keys[i];
        float out = 0.0f;
        if (k > prefix) {
            out = fmaxf(key2f(k), 0.0f);
        } else if (k == prefix) {
            bool keep;
            if (m <= remaining || m > MAX_TIES) {
                keep = true;
            } else {
                int r = 0;
                for (int j = 0; j < m; j++) r += (eq_idx[j] < i);
                keep = (r < remaining);
            }
            if (keep) out = fmaxf(key2f(k), 0.0f);
        }
        rowp[i] = out;
    }
}

// ---------------------------------------------------------------------------
extern "C" void kernel_launch(void* const* d_in, const int* in_sizes, int n_in,
                              void* d_out, int out_size)
{
    const float* features = (const float*)d_in[0];  // [8192, 512]
    const float* W1       = (const float*)d_in[1];  // [512]
    const float* W2       = (const float*)d_in[2];  // [512]
    float* out            = (float*)d_out;          // [8192, 8192]

    embed_kernel<<<N_ROWS, 256>>>(features, W1, W2);
    gemm_fast<<<NTRI, 256>>>(out);
    topk_select<<<N_ROWS, 256>>>(out);
    gemm_exact<<<dim3(64, 8), 256>>>(out);
    topk_final<<<N_ROWS, 256>>>(out);
}

// round 12
// speedup vs baseline: 1.8512x; 1.1431x over previous
#include <cuda_runtime.h>
#include <cuda_fp16.h>
#include <mma.h>
#include <cstdint>

using namespace nvcuda;

#define N_ROWS 8192
#define DIM    512
#define KSEL   31    // k+1 entries kept per row
#define CAP    192   // max candidates per row before full-exact fallback

// Scratch (static device arrays; no allocs allowed).
__device__ float   g_emb[N_ROWS * DIM];     // exact fp32 normalized emb
__device__ __half  g_a0 [N_ROWS * DIM];     // fp16 rounding of emb
__device__ int     g_ccnt[N_ROWS];
__device__ int     g_cand[N_ROWS * CAP];
__device__ int     g_kidx[N_ROWS * KSEL];
__device__ float   g_kval[N_ROWS * KSEL];
__device__ int     g_ambig[N_ROWS];
__device__ int     g_list [N_ROWS];
__device__ int     g_cnt;

// ---------------------------------------------------------------------------
// Kernel 1: emb = normalize( relu(f*W1)*W2 ).  Bit-matches reference (vec2
// leaf + warp shfl_down tree + warp0 tree). Emits fp16 rounding too.
// ---------------------------------------------------------------------------
__global__ __launch_bounds__(256) void embed_kernel(
    const float* __restrict__ f,
    const float* __restrict__ w1,
    const float* __restrict__ w2)
{
    const int row  = blockIdx.x;
    const int t    = threadIdx.x;
    const int lane = t & 31;
    const int warp = t >> 5;

    if (row == 0 && t == 0) g_cnt = 0;

    const float2 v = reinterpret_cast<const float2*>(f + (size_t)row * DIM)[t];
    const float2 a = reinterpret_cast<const float2*>(w1)[t];
    const float2 b = reinterpret_cast<const float2*>(w2)[t];

    float h0 = __fmul_rn(fmaxf(__fmul_rn(v.x, a.x), 0.0f), b.x);
    float h1 = __fmul_rn(fmaxf(__fmul_rn(v.y, a.y), 0.0f), b.y);

    float acc = __fadd_rn(__fmul_rn(h0, h0), __fmul_rn(h1, h1));

    #pragma unroll
    for (int off = 16; off > 0; off >>= 1)
        acc = __fadd_rn(acc, __shfl_down_sync(0xFFFFFFFFu, acc, off));

    __shared__ float s_w[8];
    __shared__ float s_nrm;
    if (lane == 0) s_w[warp] = acc;
    __syncthreads();

    if (warp == 0) {
        float x = (lane < 8) ? s_w[lane] : 0.0f;
        #pragma unroll
        for (int off = 16; off > 0; off >>= 1)
            x = __fadd_rn(x, __shfl_down_sync(0xFFFFFFFFu, x, off));
        if (lane == 0)
            s_nrm = fmaxf(__fsqrt_rn(x), 1e-12f);
    }
    __syncthreads();

    const float nrm = s_nrm;
    float ox = __fdiv_rn(h0, nrm);
    float oy = __fdiv_rn(h1, nrm);
    reinterpret_cast<float2*>(g_emb + (size_t)row * DIM)[t] =
        make_float2(ox, oy);

    __half2 p0;
    p0.x = __float2half_rn(ox);
    p0.y = __float2half_rn(oy);
    reinterpret_cast<__half2*>(g_a0 + (size_t)row * DIM)[t] = p0;
}

// ---------------------------------------------------------------------------
// Kernel 2: FAST S0 = A0 * A0^T via wmma fp16 (SINGLE pass).
// 128x128 CTA tile, 8 warps (2x4), warp tile 64x32, k-chunks of 32,
// 3-stage cp.async pipeline, one __syncthreads per stage.
// Triangle grid; direct mirror store.
// ---------------------------------------------------------------------------
#define NB     (N_ROWS / 128)
#define NTRI   (NB * (NB + 1) / 2)
#define LDT    40                      // smem pitch in halfs (80B rows)
#define KCHK   32
#define NSTAGE (DIM / KCHK)            // 16
#define TILE_H (128 * LDT)             // halfs per tile buffer
#define DYN_B  (2 * 3 * TILE_H * 2)    // 61440 bytes

__device__ __forceinline__ void cp16(uint32_t sdst, const void* gsrc) {
    asm volatile("cp.async.ca.shared.global [%0], [%1], 16;" :: "r"(sdst), "l"(gsrc));
}

__global__ __launch_bounds__(256, 1) void gemm_fast(float* __restrict__ C)
{
    extern __shared__ __align__(128) char dyn[];
    __half* const sA = reinterpret_cast<__half*>(dyn);              // 3 bufs
    __half* const sB = reinterpret_cast<__half*>(dyn) + 3 * TILE_H; // 3 bufs
    const uint32_t sA_u = (uint32_t)__cvta_generic_to_shared(sA);
    const uint32_t sB_u = (uint32_t)__cvta_generic_to_shared(sB);

    const int t5 = blockIdx.x;
    int by = (int)((2.0 * NB + 1.0 - sqrt((2.0 * NB + 1.0) * (2.0 * NB + 1.0)
                                          - 8.0 * (double)t5)) * 0.5);
    while (by > 0      && (by * NB - (by * (by - 1)) / 2) > t5) by--;
    while (by < NB - 1 && ((by + 1) * NB - ((by + 1) * by) / 2) <= t5) by++;
    const int bx = by + (t5 - (by * NB - (by * (by - 1)) / 2));

    const int rowBase = by * 128;
    const int colBase = bx * 128;

    const int tid   = threadIdx.x;
    const int wid   = tid >> 5;
    const int lane  = tid & 31;
    const int warpM = wid & 1;
    const int warpN = wid >> 1;

    wmma::fragment<wmma::accumulator, 16, 16, 16, float> c[4][2];
    #pragma unroll
    for (int i = 0; i < 4; i++)
        #pragma unroll
        for (int j = 0; j < 2; j++)
            wmma::fill_fragment(c[i][j], 0.0f);

    // Fill: 2 tiles x 128 rows x 64B = 1024 x 16B; 4 per thread.
    auto fill = [&](int buf, int s) {
        const int kc = s * KCHK;
        #pragma unroll
        for (int l = 0; l < 4; l++) {
            const int idx  = tid + l * 256;
            const int tile = idx >> 9;
            const int rem  = idx & 511;
            const int r    = rem >> 2;
            const int cc   = rem & 3;
            const int gb   = tile ? colBase : rowBase;
            const uint32_t base = tile ? sB_u : sA_u;
            cp16(base + (uint32_t)(buf * TILE_H * 2 + r * (LDT * 2) + cc * 16),
                 g_a0 + (size_t)(gb + r) * DIM + kc + cc * 8);
        }
        asm volatile("cp.async.commit_group;");
    };

    fill(0, 0);
    fill(1, 1);

    for (int s = 0; s < NSTAGE; s++) {
        if (s + 1 < NSTAGE) asm volatile("cp.async.wait_group 1;");
        else                asm volatile("cp.async.wait_group 0;");
        __syncthreads();
        if (s + 2 < NSTAGE) fill((s + 2) % 3, s + 2);

        const int b = s % 3;
        #pragma unroll
        for (int ks = 0; ks < 2; ks++) {
            wmma::fragment<wmma::matrix_a, 16, 16, 16, __half,
                           wmma::row_major> af[4];
            wmma::fragment<wmma::matrix_b, 16, 16, 16, __half,
                           wmma::col_major> bf[2];
            #pragma unroll
            for (int i = 0; i < 4; i++)
                wmma::load_matrix_sync(af[i],
                    sA + b * TILE_H + (warpM * 64 + i * 16) * LDT + ks * 16, LDT);
            #pragma unroll
            for (int j = 0; j < 2; j++)
                wmma::load_matrix_sync(bf[j],
                    sB + b * TILE_H + (warpN * 32 + j * 16) * LDT + ks * 16, LDT);
            #pragma unroll
            for (int i = 0; i < 4; i++)
                #pragma unroll
                for (int j = 0; j < 2; j++)
                    wmma::mma_sync(c[i][j], af[i], bf[j], c[i][j]);
        }
    }

    #pragma unroll
    for (int i = 0; i < 4; i++)
        #pragma unroll
        for (int j = 0; j < 2; j++) {
            const int r0 = rowBase + warpM * 64 + i * 16;
            const int c0 = colBase + warpN * 32 + j * 16;
            wmma::store_matrix_sync(C + (size_t)r0 * N_ROWS + c0, c[i][j],
                                    N_ROWS, wmma::mem_row_major);
            if (bx != by)
                wmma::store_matrix_sync(C + (size_t)c0 * N_ROWS + r0, c[i][j],
                                        N_ROWS, wmma::mem_col_major);
        }
    (void)lane;
}

// ---------------------------------------------------------------------------
__device__ __forceinline__ unsigned f2key(float v) {
    unsigned u = __float_as_uint(v);
    return (u & 0x80000000u) ? ~u : (u | 0x80000000u);
}
__device__ __forceinline__ float key2f(unsigned k) {
    unsigned u = (k & 0x80000000u) ? (k & 0x7FFFFFFFu) : ~k;
    return __uint_as_float(u);
}

// ---------------------------------------------------------------------------
// Kernel 3: per-row radix select on FAST sims -> fast s31; collect candidate
// set { j : s_j >= s31 - margin }. Overflow (> CAP) -> full-exact fallback.
// No writes to C.
// ---------------------------------------------------------------------------
__global__ __launch_bounds__(256) void topk_cand(const float* __restrict__ C)
{
    __shared__ unsigned keys[N_ROWS];
    __shared__ unsigned hist[256];
    __shared__ unsigned s_prefix;
    __shared__ int      s_rem;
    __shared__ int      s_cnt;

    const int row = blockIdx.x;
    const int tid = threadIdx.x;
    const float* __restrict__ rowp = C + (size_t)row * N_ROWS;

    for (int i = tid; i < N_ROWS / 4; i += 256) {
        float4 v = reinterpret_cast<const float4*>(rowp)[i];
        keys[i * 4 + 0] = f2key(v.x);
        keys[i * 4 + 1] = f2key(v.y);
        keys[i * 4 + 2] = f2key(v.z);
        keys[i * 4 + 3] = f2key(v.w);
    }
    if (tid == 0) s_cnt = 0;
    __syncthreads();

    unsigned prefix = 0;
    int remaining = KSEL;

    #pragma unroll
    for (int shift = 24; shift >= 0; shift -= 8) {
        hist[tid] = 0;
        __syncthreads();
        const unsigned himask = (shift == 24) ? 0u : (0xFFFFFFFFu << (shift + 8));
        for (int i = tid; i < N_ROWS; i += 256) {
            const unsigned k = keys[i];
            if ((k & himask) == prefix)
                atomicAdd(&hist[(k >> shift) & 255u], 1u);
        }
        __syncthreads();
        if (tid == 0) {
            int cum = 0, b = 255;
            for (; b >= 0; b--) {
                cum += (int)hist[b];
                if (cum >= remaining) break;
            }
            if (b < 0) b = 0;
            s_prefix = prefix | ((unsigned)b << shift);
            s_rem    = remaining - (cum - (int)hist[b]);
        }
        __syncthreads();
        prefix    = s_prefix;
        remaining = s_rem;
        __syncthreads();
    }

    // Candidate threshold: fast error bound is ~1.0e-3 * s (fp16 1-pass).
    const float thr  = key2f(prefix);
    const float cthr = __fsub_rn(thr, __fmaf_rn(3.0e-3f, thr, 2.0e-4f));
    const unsigned ckey = f2key(cthr);

    for (int i = tid; i < N_ROWS; i += 256) {
        if (keys[i] >= ckey) {
            int p = atomicAdd(&s_cnt, 1);
            if (p < CAP) g_cand[row * CAP + p] = i;
        }
    }
    __syncthreads();

    if (tid == 0) {
        if (s_cnt > CAP) {
            g_ambig[row] = 1;
            int p = atomicAdd(&g_cnt, 1);
            g_list[p] = row;
        } else {
            g_ambig[row] = 0;
            g_ccnt[row]  = s_cnt;
        }
    }
}

// ---------------------------------------------------------------------------
// Kernel 4: exact rescoring of candidates. One block (128 thr) per row.
// Each candidate's sim recomputed with the bit-identical ascending-k fp32
// FMA chain (matches reference). Rank among candidates (jax tie-break:
// value desc, index asc); top-31 written to g_kidx/g_kval by rank.
// ---------------------------------------------------------------------------
__global__ __launch_bounds__(128) void cand_exact()
{
    const int row = blockIdx.x;
    if (g_ambig[row]) return;

    __shared__ float sRow[DIM];
    __shared__ float sval[CAP];
    __shared__ int   sidx[CAP];

    const int tid = threadIdx.x;
    const int cnt = g_ccnt[row];

    for (int i = tid; i < DIM / 4; i += 128)
        reinterpret_cast<float4*>(sRow)[i] =
            reinterpret_cast<const float4*>(g_emb + (size_t)row * DIM)[i];
    __syncthreads();

    for (int t = tid; t < cnt; t += 128) {
        const int j = g_cand[row * CAP + t];
        const float4* col = reinterpret_cast<const float4*>(g_emb + (size_t)j * DIM);
        float acc = 0.0f;
        #pragma unroll 8
        for (int k4 = 0; k4 < DIM / 4; k4++) {
            const float4 cv = col[k4];
            const float4 rv = reinterpret_cast<const float4*>(sRow)[k4];
            acc = __fmaf_rn(rv.x, cv.x, acc);
            acc = __fmaf_rn(rv.y, cv.y, acc);
            acc = __fmaf_rn(rv.z, cv.z, acc);
            acc = __fmaf_rn(rv.w, cv.w, acc);
        }
        sval[t] = acc;
        sidx[t] = j;
    }
    __syncthreads();

    for (int t = tid; t < cnt; t += 128) {
        const float v   = sval[t];
        const int   idx = sidx[t];
        int rank = 0;
        for (int m = 0; m < cnt; m++) {
            const float vm = sval[m];
            rank += (vm > v) || (vm == v && sidx[m] < idx);
        }
        if (rank < KSEL) {
            g_kidx[row * KSEL + rank] = idx;
            g_kval[row * KSEL + rank] = v;
        }
    }
}

// ---------------------------------------------------------------------------
// Kernel 5: finalize — zero the row, scatter the 31 exact relu'd values.
// (Fallback rows are only zeroed; gemm_exact/topk_final overwrite them.)
// ---------------------------------------------------------------------------
__global__ __launch_bounds__(256) void finalize(float* __restrict__ C)
{
    const int row = blockIdx.x;
    const int tid = threadIdx.x;
    float* __restrict__ rowp = C + (size_t)row * N_ROWS;

    const float4 z = make_float4(0.f, 0.f, 0.f, 0.f);
    #pragma unroll
    for (int l = 0; l < 8; l++)
        reinterpret_cast<float4*>(rowp)[tid + l * 256] = z;
    __syncthreads();

    if (!g_ambig[row] && tid < KSEL) {
        const int   idx = g_kidx[row * KSEL + tid];
        const float val = g_kval[row * KSEL + tid];
        rowp[idx] = fmaxf(val, 0.0f);
    }
}

// ---------------------------------------------------------------------------
// Kernel 6 (fallback, expected empty): exact full-row sims for overflow rows.
// ---------------------------------------------------------------------------
__global__ __launch_bounds__(256) void gemm_exact(float* __restrict__ C)
{
    const int cnt = g_cnt;
    const int colBase = blockIdx.x * 128;

    for (int rt = blockIdx.y; rt * 32 < cnt; rt += 8) {
        __shared__ int   ids[32];
        __shared__ float Af[32][68];
        __shared__ float Bf[64][132];

        const int tid = threadIdx.x;
        __syncthreads();
        if (tid < 32) {
            int idx = rt * 32 + tid;
            ids[tid] = (idx < cnt) ? g_list[idx] : -1;
        }
        __syncthreads();

        const int rg = tid >> 5;
        const int cg = tid & 31;

        float acc[4][4];
        #pragma unroll
        for (int i = 0; i < 4; i++)
            #pragma unroll
            for (int j = 0; j < 4; j++)
                acc[i][j] = 0.0f;

        for (int kc = 0; kc < DIM; kc += 64) {
            #pragma unroll
            for (int l = 0; l < 2; l++) {
                const int idx = tid + l * 256;
                const int r   = idx >> 4;
                const int c4  = idx & 15;
                const int gid = ids[r];
                float4 v = make_float4(0.f, 0.f, 0.f, 0.f);
                if (gid >= 0)
                    v = *reinterpret_cast<const float4*>(
                            &g_emb[(size_t)gid * DIM + kc + c4 * 4]);
                *reinterpret_cast<float4*>(&Af[r][c4 * 4]) = v;
            }
            #pragma unroll
            for (int l = 0; l < 8; l++) {
                const int idx = tid + l * 256;
                const int col = idx >> 4;
                const int c4  = idx & 15;
                float4 v = *reinterpret_cast<const float4*>(
                    &g_emb[(size_t)(colBase + col) * DIM + kc + c4 * 4]);
                Bf[c4 * 4 + 0][col] = v.x;
                Bf[c4 * 4 + 1][col] = v.y;
                Bf[c4 * 4 + 2][col] = v.z;
                Bf[c4 * 4 + 3][col] = v.w;
            }
            __syncthreads();

            for (int k = 0; k < 64; k++) {
                float ar[4];
                #pragma unroll
                for (int i = 0; i < 4; i++) ar[i] = Af[rg * 4 + i][k];
                float4 br = *reinterpret_cast<const float4*>(&Bf[k][cg * 4]);
                #pragma unroll
                for (int i = 0; i < 4; i++) {
                    acc[i][0] = __fmaf_rn(ar[i], br.x, acc[i][0]);
                    acc[i][1] = __fmaf_rn(ar[i], br.y, acc[i][1]);
                    acc[i][2] = __fmaf_rn(ar[i], br.z, acc[i][2]);
                    acc[i][3] = __fmaf_rn(ar[i], br.w, acc[i][3]);
                }
            }
            __syncthreads();
        }

        #pragma unroll
        for (int i = 0; i < 4; i++) {
            const int gid = ids[rg * 4 + i];
            if (gid >= 0)
                *reinterpret_cast<float4*>(
                    &C[(size_t)gid * N_ROWS + colBase + cg * 4]) =
                    make_float4(acc[i][0], acc[i][1], acc[i][2], acc[i][3]);
        }
    }
}

// ---------------------------------------------------------------------------
// Kernel 7 (fallback): exact top-k (jax tie-break) on overflow rows only.
// ---------------------------------------------------------------------------
#define MAX_TIES 64

__global__ __launch_bounds__(256) void topk_final(float* __restrict__ C)
{
    const int row = blockIdx.x;
    if (!g_ambig[row]) return;

    __shared__ unsigned keys[N_ROWS];
    __shared__ unsigned hist[256];
    __shared__ unsigned s_prefix;
    __shared__ int      s_rem;
    __shared__ int      eq_idx[MAX_TIES];
    __shared__ int      eq_n;

    const int tid = threadIdx.x;
    float* __restrict__ rowp = C + (size_t)row * N_ROWS;

    for (int i = tid; i < N_ROWS; i += 256)
        keys[i] = f2key(rowp[i]);
    if (tid == 0) eq_n = 0;
    __syncthreads();

    unsigned prefix = 0;
    int remaining = KSEL;

    #pragma unroll
    for (int shift = 24; shift >= 0; shift -= 8) {
        hist[tid] = 0;
        __syncthreads();
        const unsigned himask = (shift == 24) ? 0u : (0xFFFFFFFFu << (shift + 8));
        for (int i = tid; i < N_ROWS; i += 256) {
            const unsigned k = keys[i];
            if ((k & himask) == prefix)
                atomicAdd(&hist[(k >> shift) & 255u], 1u);
        }
        __syncthreads();
        if (tid == 0) {
            int cum = 0, b = 255;
            for (; b >= 0; b--) {
                cum += (int)hist[b];
                if (cum >= remaining) break;
            }
            if (b < 0) b = 0;
            s_prefix = prefix | ((unsigned)b << shift);
            s_rem    = remaining - (cum - (int)hist[b]);
        }
        __syncthreads();
        prefix    = s_prefix;
        remaining = s_rem;
        __syncthreads();
    }

    for (int i = tid; i < N_ROWS; i += 256) {
        if (keys[i] == prefix) {
            int p = atomicAdd(&eq_n, 1);
            if (p < MAX_TIES) eq_idx[p] = i;
        }
    }
    __syncthreads();
    const int m = eq_n;

    for (int i = tid; i < N_ROWS; i += 256) {
        const unsigned k = keys[i];
        float out = 0.0f;
        if (k > prefix) {
            out = fmaxf(key2f(k), 0.0f);
        } else if (k == prefix) {
            bool keep;
            if (m <= remaining || m > MAX_TIES) {
                keep = true;
            } else {
                int r = 0;
                for (int j = 0; j < m; j++) r += (eq_idx[j] < i);
                keep = (r < remaining);
            }
            if (keep) out = fmaxf(key2f(k), 0.0f);
        }
        rowp[i] = out;
    }
}

// ---------------------------------------------------------------------------
extern "C" void kernel_launch(void* const* d_in, const int* in_sizes, int n_in,
                              void* d_out, int out_size)
{
    const float* features = (const float*)d_in[0];  // [8192, 512]
    const float* W1       = (const float*)d_in[1];  // [512]
    const float* W2       = (const float*)d_in[2];  // [512]
    float* out            = (float*)d_out;          // [8192, 8192]

    cudaFuncSetAttribute(gemm_fast,
                         cudaFuncAttributeMaxDynamicSharedMemorySize, DYN_B);

    embed_kernel<<<N_ROWS, 256>>>(features, W1, W2);
    gemm_fast<<<NTRI, 256, DYN_B>>>(out);
    topk_cand<<<N_ROWS, 256>>>(out);
    cand_exact<<<N_ROWS, 128>>>();
    finalize<<<N_ROWS, 256>>>(out);
    gemm_exact<<<dim3(64, 8), 256>>>(out);   // fallback (expected empty)
    topk_final<<<N_ROWS, 256>>>(out);        // fallback (expected empty)
}